// round 7
// baseline (speedup 1.0000x reference)
#include <cuda_runtime.h>
#include <math.h>
#include <stdint.h>

#define S_LEN   2048
#define DMODEL  1024
#define NHEADS  16
#define DKH     64
#define NBATCH  2
#define MTOT    (NBATCH * S_LEN)   // 4096
#define KTILE   64
#define NTILES  (S_LEN / KTILE)    // 32

// Scratch (allocation-free rule: __device__ globals)
__device__ float g_Qp[(size_t)MTOT * DMODEL];
__device__ float g_Kp[(size_t)MTOT * DMODEL];
__device__ float g_Vp[(size_t)MTOT * DMODEL];
__device__ float g_Vt[(size_t)NBATCH * NHEADS * DKH * S_LEN];  // [b][h][dk][s]
__device__ float g_Oh[(size_t)MTOT * DMODEL];

// ===========================================================================
// Helpers
// ===========================================================================
__device__ __forceinline__ unsigned f2tf32(float x) {
    unsigned u;
    asm("cvt.rna.tf32.f32 %0, %1;" : "=r"(u) : "f"(x));
    return u;
}
__device__ __forceinline__ float tf32f(float x) { return __uint_as_float(f2tf32(x)); }

__device__ __forceinline__ void mma_tf32(float c[4], const unsigned a[4],
                                         unsigned b0, unsigned b1) {
    asm volatile(
        "mma.sync.aligned.m16n8k8.row.col.f32.tf32.tf32.f32 "
        "{%0,%1,%2,%3}, {%4,%5,%6,%7}, {%8,%9}, {%0,%1,%2,%3};\n"
        : "+f"(c[0]), "+f"(c[1]), "+f"(c[2]), "+f"(c[3])
        : "r"(a[0]), "r"(a[1]), "r"(a[2]), "r"(a[3]), "r"(b0), "r"(b1));
}

__device__ __forceinline__ void ldsm_x4(unsigned r[4], const float* p) {
    unsigned a = (unsigned)__cvta_generic_to_shared(p);
    asm volatile("ldmatrix.sync.aligned.m8n8.x4.shared.b16 {%0,%1,%2,%3}, [%4];"
                 : "=r"(r[0]), "=r"(r[1]), "=r"(r[2]), "=r"(r[3]) : "r"(a));
}

__device__ __forceinline__ void cp16(float* dst, const float* src) {
    unsigned d = (unsigned)__cvta_generic_to_shared(dst);
    asm volatile("cp.async.cg.shared.global [%0], [%1], 16;" :: "r"(d), "l"(src));
}
__device__ __forceinline__ void cp_commit() {
    asm volatile("cp.async.commit_group;");
}
#define CP_WAIT(N) asm volatile("cp.async.wait_group %0;" :: "n"(N))

__device__ __forceinline__ void sts64f(float* p, float a, float b) {
    unsigned d = (unsigned)__cvta_generic_to_shared(p);
    asm volatile("st.shared.v2.f32 [%0], {%1,%2};" :: "r"(d), "f"(a), "f"(b) : "memory");
}

// ===========================================================================
// Projection GEMM core: C = A @ W^T + bias (optional tf32-rounded, scaled out)
// 128x128 tile, BK=32, cp.async double-buffered, XOR-swizzled, ldmatrix.
// ===========================================================================
__device__ __forceinline__ void gemm_stage(
    float* Abuf, float* Wbuf, const float* A, const float* W,
    int m0, int n0, int k0, int tid)
{
#pragma unroll
    for (int i = 0; i < 4; i++) {
        int ch = tid + 256 * i;
        int r = ch >> 3, c4 = ch & 7;
        int sc = c4 ^ (r & 7);
        cp16(Abuf + r * 32 + sc * 4, A + (size_t)(m0 + r) * 1024 + k0 + c4 * 4);
        cp16(Wbuf + r * 32 + sc * 4, W + (size_t)(n0 + r) * 1024 + k0 + c4 * 4);
    }
}

__device__ __forceinline__ void gemm_core(
    const float* __restrict__ A, const float* __restrict__ W,
    const float* __restrict__ bias, float* __restrict__ C,
    float oscale, int ocvt)
{
    extern __shared__ float gsm[];
    float* Ab0 = gsm;
    float* Ab1 = gsm + 128 * 32;
    float* Wb0 = gsm + 2 * 128 * 32;
    float* Wb1 = gsm + 3 * 128 * 32;

    int tid = threadIdx.x;
    int lane = tid & 31, warp = tid >> 5;
    int t = lane & 3;
    int mq = lane >> 3, rr = lane & 7;
    int wm = warp & 3, wn = warp >> 2;
    int m0 = blockIdx.y * 128, n0 = blockIdx.x * 128;

    float acc[2][8][4];
#pragma unroll
    for (int mf = 0; mf < 2; mf++)
#pragma unroll
        for (int nf = 0; nf < 8; nf++)
#pragma unroll
            for (int i = 0; i < 4; i++) acc[mf][nf][i] = 0.f;

    const int NK = 32;
    gemm_stage(Ab0, Wb0, A, W, m0, n0, 0, tid);
    cp_commit();
    gemm_stage(Ab1, Wb1, A, W, m0, n0, 32, tid);
    cp_commit();

    for (int ks = 0; ks < NK; ks++) {
        CP_WAIT(1);
        __syncthreads();
        const float* As_ = (ks & 1) ? Ab1 : Ab0;
        const float* Ws_ = (ks & 1) ? Wb1 : Wb0;

#pragma unroll
        for (int kk = 0; kk < 4; kk++) {
            unsigned af[2][4];
#pragma unroll
            for (int mf = 0; mf < 2; mf++) {
                int row = wm * 32 + mf * 16 + ((mq & 1) << 3) + rr;
                int sc = (kk * 2 + (mq >> 1)) ^ (row & 7);
                ldsm_x4(af[mf], As_ + row * 32 + sc * 4);
#pragma unroll
                for (int j = 0; j < 4; j++)
                    af[mf][j] = f2tf32(__uint_as_float(af[mf][j]));
            }
#pragma unroll
            for (int i = 0; i < 4; i++) {
                unsigned wf[4];
                int row = wn * 64 + (2 * i + (mq >> 1)) * 8 + rr;
                int sc = (kk * 2 + (mq & 1)) ^ (row & 7);
                ldsm_x4(wf, Ws_ + row * 32 + sc * 4);
#pragma unroll
                for (int j = 0; j < 4; j++)
                    wf[j] = f2tf32(__uint_as_float(wf[j]));
                mma_tf32(acc[0][2 * i],     af[0], wf[0], wf[1]);
                mma_tf32(acc[1][2 * i],     af[1], wf[0], wf[1]);
                mma_tf32(acc[0][2 * i + 1], af[0], wf[2], wf[3]);
                mma_tf32(acc[1][2 * i + 1], af[1], wf[2], wf[3]);
            }
        }
        __syncthreads();
        if (ks + 2 < NK) {
            float* dA = (ks & 1) ? Ab1 : Ab0;
            float* dW = (ks & 1) ? Wb1 : Wb0;
            gemm_stage(dA, dW, A, W, m0, n0, (ks + 2) * 32, tid);
        }
        cp_commit();
    }

    int g = lane >> 2;
#pragma unroll
    for (int mf = 0; mf < 2; mf++) {
        int r = m0 + wm * 32 + mf * 16 + g;
#pragma unroll
        for (int nf = 0; nf < 8; nf++) {
            int c = n0 + wn * 64 + nf * 8 + 2 * t;
            float bv0 = bias[c], bv1 = bias[c + 1];
            float v0 = acc[mf][nf][0] + bv0, v1 = acc[mf][nf][1] + bv1;
            float v2 = acc[mf][nf][2] + bv0, v3 = acc[mf][nf][3] + bv1;
            if (ocvt) {
                v0 = tf32f(v0 * oscale); v1 = tf32f(v1 * oscale);
                v2 = tf32f(v2 * oscale); v3 = tf32f(v3 * oscale);
            }
            *(float2*)&C[(size_t)r * 1024 + c] = make_float2(v0, v1);
            *(float2*)&C[(size_t)(r + 8) * 1024 + c] = make_float2(v2, v3);
        }
    }
}

// Fused Q/K/V projection: blockIdx.z selects the GEMM.
__global__ __launch_bounds__(256) void qkv_gemm(
    const float* __restrict__ q, const float* __restrict__ k,
    const float* __restrict__ v,
    const float* __restrict__ wq, const float* __restrict__ bq,
    const float* __restrict__ wk, const float* __restrict__ bk,
    const float* __restrict__ wv, const float* __restrict__ bv,
    float* __restrict__ Qp, float* __restrict__ Kp, float* __restrict__ Vp)
{
    if (blockIdx.z == 0)      gemm_core(q, wq, bq, Qp, 0.125f, 1);
    else if (blockIdx.z == 1) gemm_core(k, wk, bk, Kp, 1.0f, 1);
    else                      gemm_core(v, wv, bv, Vp, 1.0f, 0);
}

__global__ __launch_bounds__(256) void gemm_bias_tf32(
    const float* __restrict__ A, const float* __restrict__ W,
    const float* __restrict__ bias, float* __restrict__ C,
    float oscale, int ocvt)
{
    gemm_core(A, W, bias, C, oscale, ocvt);
}

// ===========================================================================
// V transpose: Vp[b*2048+s][h*64+dk] -> Vt[((b*16+h)*64+dk)*2048 + s], tf32.
// ===========================================================================
__global__ __launch_bounds__(256) void vtrans_kernel(
    const float* __restrict__ Vp, float* __restrict__ Vt)
{
    __shared__ float ts[64][65];
    int tid = threadIdx.x;
    int st = blockIdx.x, h = blockIdx.y, b = blockIdx.z;

    const float* src = Vp + ((size_t)(b * S_LEN + st * 64)) * DMODEL + h * DKH;
#pragma unroll
    for (int i = 0; i < 4; i++) {
        int id = tid + 256 * i;
        int r = id >> 4, c4 = id & 15;
        float4 v = *(const float4*)&src[(size_t)r * DMODEL + c4 * 4];
        ts[r][c4 * 4 + 0] = v.x; ts[r][c4 * 4 + 1] = v.y;
        ts[r][c4 * 4 + 2] = v.z; ts[r][c4 * 4 + 3] = v.w;
    }
    __syncthreads();
    float* dst = Vt + ((size_t)((b * NHEADS + h) * DKH)) * S_LEN + st * 64;
#pragma unroll
    for (int i = 0; i < 4; i++) {
        int id = tid + 256 * i;
        int dk = id >> 4, c4 = id & 15;
        int s0 = c4 * 4;
        float4 v;
        v.x = tf32f(ts[s0 + 0][dk]); v.y = tf32f(ts[s0 + 1][dk]);
        v.z = tf32f(ts[s0 + 2][dk]); v.w = tf32f(ts[s0 + 3][dk]);
        *(float4*)&dst[(size_t)dk * S_LEN + s0] = v;
    }
}

// ===========================================================================
// Fused attention (mma.sync, 4M x 2N warps, two-phase, no max-pass).
// Occupancy 2: smem 97KB (V double-buffered), regs capped at 128.
// SMEM float offsets:
//   QP [0,8192)  K0 [8192,12288) K1 [12288,16384)
//   V0 [16384,20480) V1 [20480,24576)  SUMS [24576,24832)
// ===========================================================================
#define SM_QP   0
#define SM_K0   8192
#define SM_K1   12288
#define SM_V0   16384
#define SM_V1   20480
#define SM_SUMS 24576
#define ATTN_SMEM (24832 * 4)   // 99328 B = 97 KiB

__device__ __forceinline__ void stage_K64(float* buf, const float* Kg, int kt, int tid) {
#pragma unroll
    for (int i = 0; i < 4; i++) {
        int id = tid + 256 * i;
        int r = id >> 4, c = id & 15;
        cp16(buf + (c >> 3) * 2048 + r * 32 + (((c & 7) ^ (r & 7)) << 2),
             Kg + (size_t)(kt * KTILE + r) * DMODEL + c * 4);
    }
}
__device__ __forceinline__ void stage_V64(float* buf, const float* Vg, int kt, int tid) {
#pragma unroll
    for (int i = 0; i < 4; i++) {
        int id = tid + 256 * i;
        int r = id >> 4, c = id & 15;   // r = dk row, c = key chunk
        cp16(buf + (c >> 3) * 2048 + r * 32 + (((c & 7) ^ (r & 7)) << 2),
             Vg + (size_t)r * S_LEN + kt * KTILE + c * 4);
    }
}

__global__ __launch_bounds__(256, 2) void attn_mma(
    const float* __restrict__ Qp, const float* __restrict__ Kp,
    const float* __restrict__ Vt, float* __restrict__ attn,
    float* __restrict__ Oh)
{
    extern __shared__ float sm[];
    float* QP = sm + SM_QP;
    float* Kb[2] = { sm + SM_K0, sm + SM_K1 };
    float* Vb[2] = { sm + SM_V0, sm + SM_V1 };
    float* SUMS = sm + SM_SUMS;

    int tid = threadIdx.x, lane = tid & 31, warp = tid >> 5;
    int g = lane >> 2, t = lane & 3;
    int mq = lane >> 3, rr = lane & 7;
    int wm = warp & 3, wn = warp >> 2;
    int qt = blockIdx.x, h = blockIdx.y, b = blockIdx.z;
    int qbase = qt * 128;

    const float* Qg = Qp + (size_t)(b * S_LEN + qbase) * DMODEL + h * DKH;
    const float* Kg = Kp + (size_t)(b * S_LEN) * DMODEL + h * DKH;
    const float* Vg = Vt + (size_t)((b * NHEADS + h) * DKH) * S_LEN;
    float* attng = attn + ((size_t)(b * NHEADS + h) * S_LEN + qbase) * S_LEN;

    // ---- prologue: stage Q + K0 (group 0), K1 (group 1) ----
#pragma unroll
    for (int i = 0; i < 8; i++) {
        int id = tid + 256 * i;
        int r = id >> 4, c = id & 15;
        cp16(QP + (c >> 3) * 4096 + r * 32 + (((c & 7) ^ (r & 7)) << 2),
             Qg + (size_t)r * DMODEL + c * 4);
    }
    stage_K64(Kb[0], Kg, 0, tid);
    cp_commit();
    stage_K64(Kb[1], Kg, 1, tid);
    cp_commit();

    CP_WAIT(1);
    __syncthreads();

    // ---- Q A-fragments in registers (64 regs), already tf32 ----
    unsigned qa[2][8][4];
#pragma unroll
    for (int mf = 0; mf < 2; mf++)
#pragma unroll
        for (int ks = 0; ks < 8; ks++) {
            int row = wm * 32 + mf * 16 + ((mq & 1) << 3) + rr;
            int sc = (((ks & 3) << 1) + (mq >> 1)) ^ (row & 7);
            ldsm_x4(qa[mf][ks], QP + (ks >> 2) * 4096 + row * 32 + sc * 4);
        }

    float l[4] = {0.f, 0.f, 0.f, 0.f};   // row sums: [mf*2 + (0:row g,1:row g+8)]

    // =================== Phase A: softmax denominators ===================
    for (int kt = 0; kt < NTILES; kt++) {
        if (kt > 0) { CP_WAIT(1); __syncthreads(); }
        const float* Ks_ = Kb[kt & 1];

#pragma unroll
        for (int i = 0; i < 2; i++) {           // 16-col halves (reg relief)
            float s2[2][2][4];
#pragma unroll
            for (int mf = 0; mf < 2; mf++)
#pragma unroll
                for (int nf = 0; nf < 2; nf++)
#pragma unroll
                    for (int j = 0; j < 4; j++) s2[mf][nf][j] = 0.f;

#pragma unroll
            for (int ks = 0; ks < 8; ks++) {
                unsigned kb[4];
                int row = wn * 32 + i * 16 + ((mq >> 1) << 3) + rr;
                int sc = (((ks & 3) << 1) + (mq & 1)) ^ (row & 7);
                ldsm_x4(kb, Ks_ + (ks >> 2) * 2048 + row * 32 + sc * 4);
                mma_tf32(s2[0][0], qa[0][ks], kb[0], kb[1]);
                mma_tf32(s2[0][1], qa[0][ks], kb[2], kb[3]);
                mma_tf32(s2[1][0], qa[1][ks], kb[0], kb[1]);
                mma_tf32(s2[1][1], qa[1][ks], kb[2], kb[3]);
            }
#pragma unroll
            for (int mf = 0; mf < 2; mf++)
#pragma unroll
                for (int nf = 0; nf < 2; nf++) {
                    l[mf * 2 + 0] += __expf(s2[mf][nf][0]) + __expf(s2[mf][nf][1]);
                    l[mf * 2 + 1] += __expf(s2[mf][nf][2]) + __expf(s2[mf][nf][3]);
                }
        }
        __syncthreads();
        if (kt + 2 < NTILES) stage_K64(Kb[kt & 1], Kg, kt + 2, tid);
        cp_commit();
    }

    // ---- combine row sums across the 2 N-groups ----
    CP_WAIT(0);
    __syncthreads();
#pragma unroll
    for (int i = 0; i < 4; i++) {
        l[i] += __shfl_xor_sync(0xffffffffu, l[i], 1);
        l[i] += __shfl_xor_sync(0xffffffffu, l[i], 2);
    }
    if (t == 0) {
#pragma unroll
        for (int mf = 0; mf < 2; mf++) {
            SUMS[wn * 128 + wm * 32 + mf * 16 + g]     = l[mf * 2 + 0];
            SUMS[wn * 128 + wm * 32 + mf * 16 + g + 8] = l[mf * 2 + 1];
        }
    }
    __syncthreads();
    float invl[4];
#pragma unroll
    for (int mf = 0; mf < 2; mf++) {
        int r1 = wm * 32 + mf * 16 + g;
        invl[mf * 2 + 0] = 1.f / (SUMS[r1] + SUMS[128 + r1]);
        invl[mf * 2 + 1] = 1.f / (SUMS[r1 + 8] + SUMS[128 + r1 + 8]);
    }
    __syncthreads();

    float o[2][4][4];
#pragma unroll
    for (int mf = 0; mf < 2; mf++)
#pragma unroll
        for (int nf = 0; nf < 4; nf++)
#pragma unroll
            for (int i = 0; i < 4; i++) o[mf][nf][i] = 0.f;

    // ---- restage: K0,V0,K1,V1 (4 groups outstanding) ----
    stage_K64(Kb[0], Kg, 0, tid); cp_commit();
    stage_V64(Vb[0], Vg, 0, tid); cp_commit();
    stage_K64(Kb[1], Kg, 1, tid); cp_commit();
    stage_V64(Vb[1], Vg, 1, tid); cp_commit();

    // =================== Phase B: attn write + O accumulation =============
    for (int kt = 0; kt < NTILES; kt++) {
        CP_WAIT(2);                 // K[kt], V[kt] done; K[kt+1], V[kt+1] in flight
        __syncthreads();            // also: prev tile's P reads complete
        const float* Ks_ = Kb[kt & 1];
        const float* Vs_ = Vb[kt & 1];

        // ---- S = QK^T, normalize, write attn, park tf32 P in QP smem ----
#pragma unroll
        for (int i = 0; i < 2; i++) {
            float s2[2][2][4];
#pragma unroll
            for (int mf = 0; mf < 2; mf++)
#pragma unroll
                for (int nf = 0; nf < 2; nf++)
#pragma unroll
                    for (int j = 0; j < 4; j++) s2[mf][nf][j] = 0.f;

#pragma unroll
            for (int ks = 0; ks < 8; ks++) {
                unsigned kb[4];
                int row = wn * 32 + i * 16 + ((mq >> 1) << 3) + rr;
                int sc = (((ks & 3) << 1) + (mq & 1)) ^ (row & 7);
                ldsm_x4(kb, Ks_ + (ks >> 2) * 2048 + row * 32 + sc * 4);
                mma_tf32(s2[0][0], qa[0][ks], kb[0], kb[1]);
                mma_tf32(s2[0][1], qa[0][ks], kb[2], kb[3]);
                mma_tf32(s2[1][0], qa[1][ks], kb[0], kb[1]);
                mma_tf32(s2[1][1], qa[1][ks], kb[2], kb[3]);
            }

#pragma unroll
            for (int mf = 0; mf < 2; mf++) {
                int r1 = wm * 32 + mf * 16 + g;
#pragma unroll
                for (int nf = 0; nf < 2; nf++) {
                    float p0 = __expf(s2[mf][nf][0]) * invl[mf * 2 + 0];
                    float p1 = __expf(s2[mf][nf][1]) * invl[mf * 2 + 0];
                    float p2 = __expf(s2[mf][nf][2]) * invl[mf * 2 + 1];
                    float p3 = __expf(s2[mf][nf][3]) * invl[mf * 2 + 1];

                    int cl = wn * 32 + (i * 2 + nf) * 8 + 2 * t;   // local col
                    int col = kt * KTILE + cl;
                    *(float2*)&attng[(size_t)r1 * S_LEN + col] = make_float2(p0, p1);
                    *(float2*)&attng[(size_t)(r1 + 8) * S_LEN + col] = make_float2(p2, p3);

                    int c4 = (cl >> 2) & 7, lo = (t & 1) * 2;
                    sts64f(QP + wn * 4096 + r1 * 32 + ((c4 ^ (r1 & 7)) << 2) + lo,
                           tf32f(p0), tf32f(p1));
                    int r2 = r1 + 8;
                    sts64f(QP + wn * 4096 + r2 * 32 + ((c4 ^ (r2 & 7)) << 2) + lo,
                           tf32f(p2), tf32f(p3));
                }
            }
        }
        __syncthreads();            // P visible; K[kt] reads complete

        if (kt + 2 < NTILES) stage_K64(Kb[kt & 1], Kg, kt + 2, tid);
        cp_commit();

        // ---- O += P @ V ----
#pragma unroll
        for (int ks = 0; ks < 8; ks++) {
            unsigned pa[2][4];
#pragma unroll
            for (int mf = 0; mf < 2; mf++) {
                int row = wm * 32 + mf * 16 + ((mq & 1) << 3) + rr;
                int sc = (((ks & 3) << 1) + (mq >> 1)) ^ (row & 7);
                ldsm_x4(pa[mf], QP + (ks >> 2) * 4096 + row * 32 + sc * 4);
            }
#pragma unroll
            for (int i = 0; i < 2; i++) {
                unsigned vb[4];
                int row = wn * 32 + i * 16 + ((mq >> 1) << 3) + rr;
                int sc = (((ks & 3) << 1) + (mq & 1)) ^ (row & 7);
                ldsm_x4(vb, Vs_ + (ks >> 2) * 2048 + row * 32 + sc * 4);
                mma_tf32(o[0][2 * i],     pa[0], vb[0], vb[1]);
                mma_tf32(o[0][2 * i + 1], pa[0], vb[2], vb[3]);
                mma_tf32(o[1][2 * i],     pa[1], vb[0], vb[1]);
                mma_tf32(o[1][2 * i + 1], pa[1], vb[2], vb[3]);
            }
        }
        __syncthreads();            // V[kt] reads complete before restage

        if (kt + 2 < NTILES) stage_V64(Vb[kt & 1], Vg, kt + 2, tid);
        cp_commit();
    }

    // =================== O epilogue (merged-head [B,S,D]) ===================
#pragma unroll
    for (int mf = 0; mf < 2; mf++) {
        int row = b * S_LEN + qbase + wm * 32 + mf * 16 + g;
        float* Og = Oh + (size_t)row * DMODEL + h * DKH;
#pragma unroll
        for (int nf = 0; nf < 4; nf++) {
            int c = wn * 32 + nf * 8 + 2 * t;
            *(float2*)&Og[c] = make_float2(o[mf][nf][0], o[mf][nf][1]);
            *(float2*)&Og[(size_t)8 * DMODEL + c] =
                make_float2(o[mf][nf][2], o[mf][nf][3]);
        }
    }
}

// ===========================================================================
extern "C" void kernel_launch(void* const* d_in, const int* in_sizes, int n_in,
                              void* d_out, int out_size)
{
    const float* q  = (const float*)d_in[0];
    const float* k  = (const float*)d_in[1];
    const float* v  = (const float*)d_in[2];
    const float* wq = (const float*)d_in[3];
    const float* bq = (const float*)d_in[4];
    const float* wk = (const float*)d_in[5];
    const float* bk = (const float*)d_in[6];
    const float* wv = (const float*)d_in[7];
    const float* bv = (const float*)d_in[8];
    const float* wo = (const float*)d_in[9];
    const float* bo = (const float*)d_in[10];

    float* out      = (float*)d_out;
    float* attn_out = out + (size_t)MTOT * DMODEL;   // tuple order: (out, attn)

    float *Qp, *Kp, *Vp, *Vt, *Oh;
    cudaGetSymbolAddress((void**)&Qp, g_Qp);
    cudaGetSymbolAddress((void**)&Kp, g_Kp);
    cudaGetSymbolAddress((void**)&Vp, g_Vp);
    cudaGetSymbolAddress((void**)&Vt, g_Vt);
    cudaGetSymbolAddress((void**)&Oh, g_Oh);

    const int gemm_smem = 4 * 128 * 32 * 4;   // 64 KiB
    cudaFuncSetAttribute(qkv_gemm, cudaFuncAttributeMaxDynamicSharedMemorySize,
                         gemm_smem);
    cudaFuncSetAttribute(gemm_bias_tf32, cudaFuncAttributeMaxDynamicSharedMemorySize,
                         gemm_smem);
    cudaFuncSetAttribute(attn_mma, cudaFuncAttributeMaxDynamicSharedMemorySize,
                         ATTN_SMEM);

    // Fused Q/K/V projections: Q pre-scaled 1/8 + tf32, K tf32, V raw.
    qkv_gemm<<<dim3(DMODEL / 128, MTOT / 128, 3), 256, gemm_smem>>>(
        q, k, v, wq, bq, wk, bk, wv, bv, Qp, Kp, Vp);

    vtrans_kernel<<<dim3(S_LEN / 64, NHEADS, NBATCH), 256>>>(Vp, Vt);

    attn_mma<<<dim3(S_LEN / 128, NHEADS, NBATCH), 256, ATTN_SMEM>>>(
        Qp, Kp, Vt, attn_out, Oh);

    gemm_bias_tf32<<<dim3(DMODEL / 128, MTOT / 128), 256, gemm_smem>>>(
        Oh, wo, bo, out, 1.0f, 0);
}

// round 8
// speedup vs baseline: 1.0172x; 1.0172x over previous
#include <cuda_runtime.h>
#include <math.h>
#include <stdint.h>

#define S_LEN   2048
#define DMODEL  1024
#define NHEADS  16
#define DKH     64
#define NBATCH  2
#define MTOT    (NBATCH * S_LEN)   // 4096
#define KTILE   64
#define NTILES  (S_LEN / KTILE)    // 32

// Scratch (allocation-free rule: __device__ globals)
__device__ float g_Qp[(size_t)MTOT * DMODEL];
__device__ float g_Kp[(size_t)MTOT * DMODEL];
__device__ float g_Vp[(size_t)MTOT * DMODEL];
__device__ float g_Vt[(size_t)NBATCH * NHEADS * DKH * S_LEN];  // [b][h][dk][s]
__device__ float g_Oh[(size_t)MTOT * DMODEL];

// ===========================================================================
// Helpers
// ===========================================================================
__device__ __forceinline__ unsigned f2tf32(float x) {
    unsigned u;
    asm("cvt.rna.tf32.f32 %0, %1;" : "=r"(u) : "f"(x));
    return u;
}
__device__ __forceinline__ float tf32f(float x) { return __uint_as_float(f2tf32(x)); }

__device__ __forceinline__ void mma_tf32(float c[4], const unsigned a[4],
                                         unsigned b0, unsigned b1) {
    asm volatile(
        "mma.sync.aligned.m16n8k8.row.col.f32.tf32.tf32.f32 "
        "{%0,%1,%2,%3}, {%4,%5,%6,%7}, {%8,%9}, {%0,%1,%2,%3};\n"
        : "+f"(c[0]), "+f"(c[1]), "+f"(c[2]), "+f"(c[3])
        : "r"(a[0]), "r"(a[1]), "r"(a[2]), "r"(a[3]), "r"(b0), "r"(b1));
}

__device__ __forceinline__ void ldsm_x4(unsigned r[4], const float* p) {
    unsigned a = (unsigned)__cvta_generic_to_shared(p);
    asm volatile("ldmatrix.sync.aligned.m8n8.x4.shared.b16 {%0,%1,%2,%3}, [%4];"
                 : "=r"(r[0]), "=r"(r[1]), "=r"(r[2]), "=r"(r[3]) : "r"(a));
}

__device__ __forceinline__ void cp16(float* dst, const float* src) {
    unsigned d = (unsigned)__cvta_generic_to_shared(dst);
    asm volatile("cp.async.cg.shared.global [%0], [%1], 16;" :: "r"(d), "l"(src));
}
__device__ __forceinline__ void cp_commit() {
    asm volatile("cp.async.commit_group;");
}
#define CP_WAIT(N) asm volatile("cp.async.wait_group %0;" :: "n"(N))

__device__ __forceinline__ void sts64f(float* p, float a, float b) {
    unsigned d = (unsigned)__cvta_generic_to_shared(p);
    asm volatile("st.shared.v2.f32 [%0], {%1,%2};" :: "r"(d), "f"(a), "f"(b) : "memory");
}

// ===========================================================================
// Projection GEMM core (proven): C = A @ W^T + bias, optional tf32 out.
// ===========================================================================
__device__ __forceinline__ void gemm_stage(
    float* Abuf, float* Wbuf, const float* A, const float* W,
    int m0, int n0, int k0, int tid)
{
#pragma unroll
    for (int i = 0; i < 4; i++) {
        int ch = tid + 256 * i;
        int r = ch >> 3, c4 = ch & 7;
        int sc = c4 ^ (r & 7);
        cp16(Abuf + r * 32 + sc * 4, A + (size_t)(m0 + r) * 1024 + k0 + c4 * 4);
        cp16(Wbuf + r * 32 + sc * 4, W + (size_t)(n0 + r) * 1024 + k0 + c4 * 4);
    }
}

__device__ __forceinline__ void gemm_core(
    const float* __restrict__ A, const float* __restrict__ W,
    const float* __restrict__ bias, float* __restrict__ C,
    float oscale, int ocvt)
{
    extern __shared__ float gsm[];
    float* Ab0 = gsm;
    float* Ab1 = gsm + 128 * 32;
    float* Wb0 = gsm + 2 * 128 * 32;
    float* Wb1 = gsm + 3 * 128 * 32;

    int tid = threadIdx.x;
    int lane = tid & 31, warp = tid >> 5;
    int t = lane & 3;
    int mq = lane >> 3, rr = lane & 7;
    int wm = warp & 3, wn = warp >> 2;
    int m0 = blockIdx.y * 128, n0 = blockIdx.x * 128;

    float acc[2][8][4];
#pragma unroll
    for (int mf = 0; mf < 2; mf++)
#pragma unroll
        for (int nf = 0; nf < 8; nf++)
#pragma unroll
            for (int i = 0; i < 4; i++) acc[mf][nf][i] = 0.f;

    const int NK = 32;
    gemm_stage(Ab0, Wb0, A, W, m0, n0, 0, tid);
    cp_commit();
    gemm_stage(Ab1, Wb1, A, W, m0, n0, 32, tid);
    cp_commit();

    for (int ks = 0; ks < NK; ks++) {
        CP_WAIT(1);
        __syncthreads();
        const float* As_ = (ks & 1) ? Ab1 : Ab0;
        const float* Ws_ = (ks & 1) ? Wb1 : Wb0;

#pragma unroll
        for (int kk = 0; kk < 4; kk++) {
            unsigned af[2][4];
#pragma unroll
            for (int mf = 0; mf < 2; mf++) {
                int row = wm * 32 + mf * 16 + ((mq & 1) << 3) + rr;
                int sc = (kk * 2 + (mq >> 1)) ^ (row & 7);
                ldsm_x4(af[mf], As_ + row * 32 + sc * 4);
#pragma unroll
                for (int j = 0; j < 4; j++)
                    af[mf][j] = f2tf32(__uint_as_float(af[mf][j]));
            }
#pragma unroll
            for (int i = 0; i < 4; i++) {
                unsigned wf[4];
                int row = wn * 64 + (2 * i + (mq >> 1)) * 8 + rr;
                int sc = (kk * 2 + (mq & 1)) ^ (row & 7);
                ldsm_x4(wf, Ws_ + row * 32 + sc * 4);
#pragma unroll
                for (int j = 0; j < 4; j++)
                    wf[j] = f2tf32(__uint_as_float(wf[j]));
                mma_tf32(acc[0][2 * i],     af[0], wf[0], wf[1]);
                mma_tf32(acc[1][2 * i],     af[1], wf[0], wf[1]);
                mma_tf32(acc[0][2 * i + 1], af[0], wf[2], wf[3]);
                mma_tf32(acc[1][2 * i + 1], af[1], wf[2], wf[3]);
            }
        }
        __syncthreads();
        if (ks + 2 < NK) {
            float* dA = (ks & 1) ? Ab1 : Ab0;
            float* dW = (ks & 1) ? Wb1 : Wb0;
            gemm_stage(dA, dW, A, W, m0, n0, (ks + 2) * 32, tid);
        }
        cp_commit();
    }

    int g = lane >> 2;
#pragma unroll
    for (int mf = 0; mf < 2; mf++) {
        int r = m0 + wm * 32 + mf * 16 + g;
#pragma unroll
        for (int nf = 0; nf < 8; nf++) {
            int c = n0 + wn * 64 + nf * 8 + 2 * t;
            float bv0 = bias[c], bv1 = bias[c + 1];
            float v0 = acc[mf][nf][0] + bv0, v1 = acc[mf][nf][1] + bv1;
            float v2 = acc[mf][nf][2] + bv0, v3 = acc[mf][nf][3] + bv1;
            if (ocvt) {
                v0 = tf32f(v0 * oscale); v1 = tf32f(v1 * oscale);
                v2 = tf32f(v2 * oscale); v3 = tf32f(v3 * oscale);
            }
            *(float2*)&C[(size_t)r * 1024 + c] = make_float2(v0, v1);
            *(float2*)&C[(size_t)(r + 8) * 1024 + c] = make_float2(v2, v3);
        }
    }
}

// Fused Q/K/V projection: blockIdx.z selects the GEMM.
__global__ __launch_bounds__(256) void qkv_gemm(
    const float* __restrict__ q, const float* __restrict__ k,
    const float* __restrict__ v,
    const float* __restrict__ wq, const float* __restrict__ bq,
    const float* __restrict__ wk, const float* __restrict__ bk,
    const float* __restrict__ wv, const float* __restrict__ bv,
    float* __restrict__ Qp, float* __restrict__ Kp, float* __restrict__ Vp)
{
    if (blockIdx.z == 0)      gemm_core(q, wq, bq, Qp, 0.125f, 1);
    else if (blockIdx.z == 1) gemm_core(k, wk, bk, Kp, 1.0f, 1);
    else                      gemm_core(v, wv, bv, Vp, 1.0f, 0);
}

__global__ __launch_bounds__(256) void gemm_bias_tf32(
    const float* __restrict__ A, const float* __restrict__ W,
    const float* __restrict__ bias, float* __restrict__ C,
    float oscale, int ocvt)
{
    gemm_core(A, W, bias, C, oscale, ocvt);
}

// ===========================================================================
// V transpose: Vp[b*2048+s][h*64+dk] -> Vt[((b*16+h)*64+dk)*2048 + s], tf32.
// ===========================================================================
__global__ __launch_bounds__(256) void vtrans_kernel(
    const float* __restrict__ Vp, float* __restrict__ Vt)
{
    __shared__ float ts[64][65];
    int tid = threadIdx.x;
    int st = blockIdx.x, h = blockIdx.y, b = blockIdx.z;

    const float* src = Vp + ((size_t)(b * S_LEN + st * 64)) * DMODEL + h * DKH;
#pragma unroll
    for (int i = 0; i < 4; i++) {
        int id = tid + 256 * i;
        int r = id >> 4, c4 = id & 15;
        float4 v = *(const float4*)&src[(size_t)r * DMODEL + c4 * 4];
        ts[r][c4 * 4 + 0] = v.x; ts[r][c4 * 4 + 1] = v.y;
        ts[r][c4 * 4 + 2] = v.z; ts[r][c4 * 4 + 3] = v.w;
    }
    __syncthreads();
    float* dst = Vt + ((size_t)((b * NHEADS + h) * DKH)) * S_LEN + st * 64;
#pragma unroll
    for (int i = 0; i < 4; i++) {
        int id = tid + 256 * i;
        int dk = id >> 4, c4 = id & 15;
        int s0 = c4 * 4;
        float4 v;
        v.x = tf32f(ts[s0 + 0][dk]); v.y = tf32f(ts[s0 + 1][dk]);
        v.z = tf32f(ts[s0 + 2][dk]); v.w = tf32f(ts[s0 + 3][dk]);
        *(float4*)&dst[(size_t)dk * S_LEN + s0] = v;
    }
}

// ===========================================================================
// Fused attention: 64-q-row blocks, 128 threads = 4 warps x 16 rows x 64 cols.
// Two-phase, no max-pass. Occupancy 2 (96 KB smem, ~120 regs, no caps hit).
// SMEM float offsets (segments of [64][32], XOR-swizzled):
//   QP [0,4096)  (Q tile; reused as P in phase B)
//   K0 [4096,8192) K1 [8192,12288)
//   V0 [12288,16384) V1 [16384,20480) V2 [20480,24576)
// ===========================================================================
#define SM_QP 0
#define SM_K0 4096
#define SM_V0 12288
#define ATTN_SMEM (24576 * 4)   // 96 KiB

__device__ __forceinline__ void stage_K64a(float* buf, const float* Kg, int kt, int tid) {
#pragma unroll
    for (int i = 0; i < 8; i++) {
        int id = tid + 128 * i;
        int r = id >> 4, c = id & 15;
        cp16(buf + (c >> 3) * 2048 + r * 32 + (((c & 7) ^ (r & 7)) << 2),
             Kg + (size_t)(kt * KTILE + r) * DMODEL + c * 4);
    }
}
__device__ __forceinline__ void stage_V64a(float* buf, const float* Vg, int kt, int tid) {
#pragma unroll
    for (int i = 0; i < 8; i++) {
        int id = tid + 128 * i;
        int r = id >> 4, c = id & 15;   // r = dk row, c = key chunk
        cp16(buf + (c >> 3) * 2048 + r * 32 + (((c & 7) ^ (r & 7)) << 2),
             Vg + (size_t)r * S_LEN + kt * KTILE + c * 4);
    }
}

__global__ __launch_bounds__(128, 2) void attn_mma(
    const float* __restrict__ Qp, const float* __restrict__ Kp,
    const float* __restrict__ Vt, float* __restrict__ attn,
    float* __restrict__ Oh)
{
    extern __shared__ float sm[];
    float* QP = sm + SM_QP;
    float* Kb[2] = { sm + SM_K0, sm + SM_K0 + 4096 };
    float* Vb[3] = { sm + SM_V0, sm + SM_V0 + 4096, sm + SM_V0 + 8192 };

    int tid = threadIdx.x, lane = tid & 31, wm = tid >> 5;
    int g = lane >> 2, t = lane & 3;
    int mq = lane >> 3, rr = lane & 7;
    int qt = blockIdx.x, h = blockIdx.y, b = blockIdx.z;
    int qbase = qt * 64;
    int r0 = wm * 16;

    const float* Qg = Qp + (size_t)(b * S_LEN + qbase) * DMODEL + h * DKH;
    const float* Kg = Kp + (size_t)(b * S_LEN) * DMODEL + h * DKH;
    const float* Vg = Vt + (size_t)((b * NHEADS + h) * DKH) * S_LEN;
    float* attng = attn + ((size_t)(b * NHEADS + h) * S_LEN + qbase) * S_LEN;

    // ---- prologue: stage Q + K0 (group 0), K1 (group 1) ----
#pragma unroll
    for (int i = 0; i < 8; i++) {
        int id = tid + 128 * i;
        int r = id >> 4, c = id & 15;
        cp16(QP + (c >> 3) * 2048 + r * 32 + (((c & 7) ^ (r & 7)) << 2),
             Qg + (size_t)r * DMODEL + c * 4);
    }
    stage_K64a(Kb[0], Kg, 0, tid);
    cp_commit();
    stage_K64a(Kb[1], Kg, 1, tid);
    cp_commit();

    CP_WAIT(1);
    __syncthreads();

    // ---- Q A-fragments in registers (32 regs), already tf32 ----
    unsigned qa[8][4];
#pragma unroll
    for (int ks = 0; ks < 8; ks++) {
        int row = r0 + ((mq & 1) << 3) + rr;
        int sc = (((ks & 3) << 1) + (mq >> 1)) ^ (row & 7);
        ldsm_x4(qa[ks], QP + (ks >> 2) * 2048 + row * 32 + sc * 4);
    }

    float l0 = 0.f, l1 = 0.f;   // row sums for rows r0+g, r0+g+8

    // =================== Phase A: softmax denominators ===================
    for (int kt = 0; kt < NTILES; kt++) {
        if (kt > 0) { CP_WAIT(1); __syncthreads(); }
        const float* Ks_ = Kb[kt & 1];

#pragma unroll
        for (int i = 0; i < 4; i++) {          // 16-col groups
            float s2[2][4];
#pragma unroll
            for (int nf = 0; nf < 2; nf++)
#pragma unroll
                for (int j = 0; j < 4; j++) s2[nf][j] = 0.f;

#pragma unroll
            for (int ks = 0; ks < 8; ks++) {
                unsigned kb[4];
                int row = i * 16 + ((mq >> 1) << 3) + rr;
                int sc = (((ks & 3) << 1) + (mq & 1)) ^ (row & 7);
                ldsm_x4(kb, Ks_ + (ks >> 2) * 2048 + row * 32 + sc * 4);
                mma_tf32(s2[0], qa[ks], kb[0], kb[1]);
                mma_tf32(s2[1], qa[ks], kb[2], kb[3]);
            }
#pragma unroll
            for (int nf = 0; nf < 2; nf++) {
                l0 += __expf(s2[nf][0]) + __expf(s2[nf][1]);
                l1 += __expf(s2[nf][2]) + __expf(s2[nf][3]);
            }
        }
        __syncthreads();
        if (kt + 2 < NTILES) stage_K64a(Kb[kt & 1], Kg, kt + 2, tid);
        cp_commit();
    }

    // ---- row sums complete after quad reduction (warp owns full rows) ----
    l0 += __shfl_xor_sync(0xffffffffu, l0, 1);
    l0 += __shfl_xor_sync(0xffffffffu, l0, 2);
    l1 += __shfl_xor_sync(0xffffffffu, l1, 1);
    l1 += __shfl_xor_sync(0xffffffffu, l1, 2);
    float invl0 = 1.f / l0, invl1 = 1.f / l1;

    float o[8][4];
#pragma unroll
    for (int nf = 0; nf < 8; nf++)
#pragma unroll
        for (int i = 0; i < 4; i++) o[nf][i] = 0.f;

    CP_WAIT(0);
    __syncthreads();

    // ---- restage K0/V0 (group 0), K1/V1 (group 1) ----
    stage_K64a(Kb[0], Kg, 0, tid); stage_V64a(Vb[0], Vg, 0, tid);
    cp_commit();
    stage_K64a(Kb[1], Kg, 1, tid); stage_V64a(Vb[1], Vg, 1, tid);
    cp_commit();

    // =================== Phase B: attn write + O accumulation =============
    for (int kt = 0; kt < NTILES; kt++) {
        CP_WAIT(1);
        __syncthreads();            // K/V[kt] ready; prev tile's P reads done
        const float* Ks_ = Kb[kt & 1];
        const float* Vs_ = Vb[kt % 3];

        // ---- S = QK^T, normalize, write attn, park tf32 P in QP smem ----
        int r1 = r0 + g, r2 = r0 + g + 8;
#pragma unroll
        for (int i = 0; i < 4; i++) {
            float s2[2][4];
#pragma unroll
            for (int nf = 0; nf < 2; nf++)
#pragma unroll
                for (int j = 0; j < 4; j++) s2[nf][j] = 0.f;

#pragma unroll
            for (int ks = 0; ks < 8; ks++) {
                unsigned kb[4];
                int row = i * 16 + ((mq >> 1) << 3) + rr;
                int sc = (((ks & 3) << 1) + (mq & 1)) ^ (row & 7);
                ldsm_x4(kb, Ks_ + (ks >> 2) * 2048 + row * 32 + sc * 4);
                mma_tf32(s2[0], qa[ks], kb[0], kb[1]);
                mma_tf32(s2[1], qa[ks], kb[2], kb[3]);
            }

#pragma unroll
            for (int nf = 0; nf < 2; nf++) {
                float p0 = __expf(s2[nf][0]) * invl0;
                float p1 = __expf(s2[nf][1]) * invl0;
                float p2 = __expf(s2[nf][2]) * invl1;
                float p3 = __expf(s2[nf][3]) * invl1;

                int cl = i * 16 + nf * 8 + 2 * t;     // local col 0..63
                int col = kt * KTILE + cl;
                *(float2*)&attng[(size_t)r1 * S_LEN + col] = make_float2(p0, p1);
                *(float2*)&attng[(size_t)r2 * S_LEN + col] = make_float2(p2, p3);

                int c4 = (cl >> 2) & 7, lo = (t & 1) * 2;
                sts64f(QP + (cl >> 5) * 2048 + r1 * 32 + ((c4 ^ (r1 & 7)) << 2) + lo,
                       tf32f(p0), tf32f(p1));
                sts64f(QP + (cl >> 5) * 2048 + r2 * 32 + ((c4 ^ (r2 & 7)) << 2) + lo,
                       tf32f(p2), tf32f(p3));
            }
        }
        __syncthreads();            // P visible; K[kt] reads complete

        if (kt + 2 < NTILES) {
            stage_K64a(Kb[kt & 1], Kg, kt + 2, tid);
            stage_V64a(Vb[(kt + 2) % 3], Vg, kt + 2, tid);
        }
        cp_commit();

        // ---- O += P @ V ----
#pragma unroll
        for (int ks = 0; ks < 8; ks++) {
            unsigned pa[4];
            {
                int row = r0 + ((mq & 1) << 3) + rr;
                int sc = (((ks & 3) << 1) + (mq >> 1)) ^ (row & 7);
                ldsm_x4(pa, QP + (ks >> 2) * 2048 + row * 32 + sc * 4);
            }
#pragma unroll
            for (int i = 0; i < 4; i++) {
                unsigned vb[4];
                int row = i * 16 + ((mq >> 1) << 3) + rr;
                int sc = (((ks & 3) << 1) + (mq & 1)) ^ (row & 7);
                ldsm_x4(vb, Vs_ + (ks >> 2) * 2048 + row * 32 + sc * 4);
                mma_tf32(o[2 * i],     pa, vb[0], vb[1]);
                mma_tf32(o[2 * i + 1], pa, vb[2], vb[3]);
            }
        }
    }

    // =================== O epilogue (merged-head [B,S,D]) ===================
    {
        int row = b * S_LEN + qbase + r0 + g;
        float* Og = Oh + (size_t)row * DMODEL + h * DKH;
#pragma unroll
        for (int nf = 0; nf < 8; nf++) {
            int c = nf * 8 + 2 * t;
            *(float2*)&Og[c] = make_float2(o[nf][0], o[nf][1]);
            *(float2*)&Og[(size_t)8 * DMODEL + c] = make_float2(o[nf][2], o[nf][3]);
        }
    }
}

// ===========================================================================
extern "C" void kernel_launch(void* const* d_in, const int* in_sizes, int n_in,
                              void* d_out, int out_size)
{
    const float* q  = (const float*)d_in[0];
    const float* k  = (const float*)d_in[1];
    const float* v  = (const float*)d_in[2];
    const float* wq = (const float*)d_in[3];
    const float* bq = (const float*)d_in[4];
    const float* wk = (const float*)d_in[5];
    const float* bk = (const float*)d_in[6];
    const float* wv = (const float*)d_in[7];
    const float* bv = (const float*)d_in[8];
    const float* wo = (const float*)d_in[9];
    const float* bo = (const float*)d_in[10];

    float* out      = (float*)d_out;
    float* attn_out = out + (size_t)MTOT * DMODEL;   // tuple order: (out, attn)

    float *Qp, *Kp, *Vp, *Vt, *Oh;
    cudaGetSymbolAddress((void**)&Qp, g_Qp);
    cudaGetSymbolAddress((void**)&Kp, g_Kp);
    cudaGetSymbolAddress((void**)&Vp, g_Vp);
    cudaGetSymbolAddress((void**)&Vt, g_Vt);
    cudaGetSymbolAddress((void**)&Oh, g_Oh);

    const int gemm_smem = 4 * 128 * 32 * 4;   // 64 KiB
    cudaFuncSetAttribute(qkv_gemm, cudaFuncAttributeMaxDynamicSharedMemorySize,
                         gemm_smem);
    cudaFuncSetAttribute(gemm_bias_tf32, cudaFuncAttributeMaxDynamicSharedMemorySize,
                         gemm_smem);
    cudaFuncSetAttribute(attn_mma, cudaFuncAttributeMaxDynamicSharedMemorySize,
                         ATTN_SMEM);

    // Fused Q/K/V projections: Q pre-scaled 1/8 + tf32, K tf32, V raw.
    qkv_gemm<<<dim3(DMODEL / 128, MTOT / 128, 3), 256, gemm_smem>>>(
        q, k, v, wq, bq, wk, bk, wv, bv, Qp, Kp, Vp);

    vtrans_kernel<<<dim3(S_LEN / 64, NHEADS, NBATCH), 256>>>(Vp, Vt);

    attn_mma<<<dim3(S_LEN / 64, NHEADS, NBATCH), 128, ATTN_SMEM>>>(
        Qp, Kp, Vt, attn_out, Oh);

    gemm_bias_tf32<<<dim3(DMODEL / 128, MTOT / 128), 256, gemm_smem>>>(
        Oh, wo, bo, out, 1.0f, 0);
}